// round 14
// baseline (speedup 1.0000x reference)
#include <cuda_runtime.h>
#include <cuda_bf16.h>

// ---------------------------------------------------------------------------
// LoongSpikeKernel: K[ch,h,l] = 2*Re( sum_n C_disc[h,n] * exp(dtA[h,n]*l) )
// H=512, NS=64 states/h, L=2048, CH=1.
//
// R14: occupancy/balance experiment. R10-R13: four different inner loops all
//   ~15.5us with nothing saturated -> either scheduling-limited at 8
//   warps/SMSP with 4-vs-3 CTA/SM imbalance (H1), or packed f32x2 is
//   secretly rt=4 (H2). Test H1: NSPLIT=2 (grid 1024, 32 k's per CTA),
//   __launch_bounds__(256,7) -> up to 14 warps/SMSP, near-perfect SM
//   balance (1024/148 = 6.92). KCH=16 so smem 18KB x 7 fits 228KB.
//   Inner loop = R13's decoupled even/odd chains (unchanged, known-good).
// ---------------------------------------------------------------------------

#define NS 64   // states per h (M*NST)
#define GS 8    // states per thread
#define NP 4    // packed state-pairs per thread
#define NLANE 32
#define NSPLIT 2
#define KCH 16  // k-iters buffered in smem per chunk

typedef unsigned long long ull;

// fp32 two-term Cody-Waite reduction + fast sincos.
__device__ __forceinline__ void sincos_cw(float x, float* s, float* c) {
    float k = rintf(x * 0.15915494309189535f);
    float r = fmaf(k, -6.28125f, x);
    r = fmaf(k, -1.9353071795864769e-3f, r);
    __sincosf(r, s, c);
}

__device__ __forceinline__ ull pack2(float lo, float hi) {
    ull r;
    asm("mov.b64 %0, {%1, %2};" : "=l"(r)
        : "r"(__float_as_uint(lo)), "r"(__float_as_uint(hi)));
    return r;
}
__device__ __forceinline__ ull add2(ull a, ull b) {
    ull r; asm("add.rn.f32x2 %0, %1, %2;" : "=l"(r) : "l"(a), "l"(b)); return r;
}
__device__ __forceinline__ ull mul2(ull a, ull b) {
    ull r; asm("mul.rn.f32x2 %0, %1, %2;" : "=l"(r) : "l"(a), "l"(b)); return r;
}
__device__ __forceinline__ ull fma2(ull a, ull b, ull c) {
    ull r; asm("fma.rn.f32x2 %0, %1, %2, %3;" : "=l"(r) : "l"(a), "l"(b), "l"(c)); return r;
}
__device__ __forceinline__ float sum2(ull a) {
    unsigned lo, hi;
    asm("mov.b64 {%0, %1}, %2;" : "=r"(lo), "=r"(hi) : "l"(a));
    return __uint_as_float(lo) + __uint_as_float(hi);
}

// ---------------------------------------------------------------------------
__global__ __launch_bounds__(256, 7) void loong_fused(
    float* __restrict__ out,
    const float* __restrict__ C_real,
    const float* __restrict__ log_dt,
    const float* __restrict__ log_A_real,
    const float* __restrict__ A_imag,
    const float* __restrict__ omega_logit,
    const float* __restrict__ eta_logit,
    int NST, int L) {
    const float OMIN = 1e-6f, OMAX = 100.0f, EMIN = 1e-6f, EMAX = 10.0f;
    const int h    = blockIdx.x;
    const int tid  = threadIdx.x;
    const int g    = tid >> 5;     // state group 0..7 (== warp id)
    const int t    = tid & 31;     // l lane 0..31

    __shared__ float2 s_dtA[NS];
    __shared__ float2 s_C2 [NS];
    __shared__ float4 s_R32[NS];              // (rr, ri, 2*Re(r32^2), -|r32^2|^2)
    __shared__ float  sR[KCH][8][NLANE];      // per-k group partials (16 KB)

    // ---- phase 0: per-CTA constants, 64 threads ----
    if (tid < NS) {
        int m = tid / NST;                    // 0..M-1
        int n = tid - m * NST;                // 0..NST-1
        int gi = h * NST + n;

        float dt    = expf(log_dt[h]);
        float omega = OMIN + (OMAX - OMIN) / (1.f + expf(-omega_logit[m]));
        float eta   = EMIN + (EMAX - EMIN) / (1.f + expf(-eta_logit[m]));
        float Are   = -expf(log_A_real[gi]);
        float Aim   = A_imag[gi];
        float Afr   = -omega + eta * Are;
        float Afi   = eta * Aim;
        float Cr    = eta * C_real[gi * 2 + 0];   // CH = 1
        float Ci    = eta * C_real[gi * 2 + 1];
        float dtAr  = Afr * dt;
        float dtAi  = Afi * dt;

        // (exp(dtA) - 1) / (A_frac + 1e-8)
        float er = expf(dtAr);
        float s1, c1; sincos_cw(dtAi, &s1, &c1);
        float nr = er * c1 - 1.f;
        float ni = er * s1;
        float dr  = Afr + 1e-8f, di = Afi;
        float inv = 1.f / (dr * dr + di * di);
        float qr  = (nr * dr + ni * di) * inv;
        float qi  = (ni * dr - nr * di) * inv;
        float Cdr = Cr * qr - Ci * qi;
        float Cdi = Cr * qi + Ci * qr;
        if (sqrtf(Afr * Afr + Afi * Afi) < 1e-6f) { Cdr = Cr * dt; Cdi = Ci * dt; }

        s_dtA[tid] = make_float2(dtAr, dtAi);
        s_C2 [tid] = make_float2(2.f * Cdr, 2.f * Cdi);

        // r32 = exp(32*dtA); chain constants use r32^2 = exp(64*dtA):
        float e32 = expf(32.f * dtAr);
        float s32, c32; sincos_cw(32.f * dtAi, &s32, &c32);
        float rr = e32 * c32, ri = e32 * s32;
        float twoa2 = 2.f * (rr * rr - ri * ri);
        float negq2 = -expf(128.f * dtAr);
        s_R32[tid] = make_float4(rr, ri, twoa2, negq2);
    }
    __syncthreads();

    // ---- phase 1: seed at l0 = t + ksplit-offset; s0..s3 = Re(w*r32^{0..3}) ----
    const int base   = g * GS;
    const int kbeg   = blockIdx.y * ((L / NLANE) / NSPLIT);   // 0 or 32
    ull ue0[NP], ue1[NP], vo0[NP], vo1[NP], twoa[NP], negq[NP];
    const float tf = (float)(t + kbeg * NLANE);
    const float E = __expf(s_dtA[base].x * tf);   // shared decay across group
#pragma unroll
    for (int p = 0; p < NP; p++) {
        float s0v[2], s1v[2], s2v[2], s3v[2], tw[2], nq[2];
#pragma unroll
        for (int e = 0; e < 2; e++) {
            int i = base + 2 * p + e;
            float2 a = s_dtA[i];
            float2 c = s_C2 [i];
            float4 q = s_R32[i];
            float s, co; sincos_cw(a.y * tf, &s, &co);   // per-state exact phase
            float xr = E * co, xi = E * s;
            float wr = c.x * xr - c.y * xi;      // w = C2 * e^{dtA l0}
            float wi = c.x * xi + c.y * xr;
            float w1r = wr * q.x - wi * q.y;     // w * r32
            float w1i = wr * q.y + wi * q.x;
            float w2r = w1r * q.x - w1i * q.y;   // w * r32^2
            float w2i = w1r * q.y + w1i * q.x;
            float w3r = w2r * q.x - w2i * q.y;   // w * r32^3 (real part only)
            s0v[e] = wr; s1v[e] = w1r; s2v[e] = w2r; s3v[e] = w3r;
            tw[e] = q.z; nq[e] = q.w;
        }
        ue0[p]  = pack2(s0v[0], s0v[1]);   // even chain: u_0 = s_0
        ue1[p]  = pack2(s2v[0], s2v[1]);   //             u_1 = s_2
        vo0[p]  = pack2(s1v[0], s1v[1]);   // odd chain:  v_0 = s_1
        vo1[p]  = pack2(s3v[0], s3v[1]);   //             v_1 = s_3
        twoa[p] = pack2(tw[0],  tw[1]);
        negq[p] = pack2(nq[0],  nq[1]);
    }

    const int kcnt = (L / NLANE) / NSPLIT;        // k's this CTA (32)
    const long long ob = (long long)h * L;

    // ---- phase 2: two independent 2nd-order chains per pair ----
    for (int kk0 = 0; kk0 < kcnt; kk0 += KCH) {
#pragma unroll
        for (int k = 0; k < KCH; k += 4) {
            sR[k    ][g][t] = sum2(add2(add2(ue0[0], ue0[1]), add2(ue0[2], ue0[3])));
            sR[k + 1][g][t] = sum2(add2(add2(vo0[0], vo0[1]), add2(vo0[2], vo0[3])));
#pragma unroll
            for (int p = 0; p < NP; p++) {
                ue0[p] = fma2(ue1[p], twoa[p], mul2(ue0[p], negq[p]));
                vo0[p] = fma2(vo1[p], twoa[p], mul2(vo0[p], negq[p]));
            }
            sR[k + 2][g][t] = sum2(add2(add2(ue1[0], ue1[1]), add2(ue1[2], ue1[3])));
            sR[k + 3][g][t] = sum2(add2(add2(vo1[0], vo1[1]), add2(vo1[2], vo1[3])));
#pragma unroll
            for (int p = 0; p < NP; p++) {
                ue1[p] = fma2(ue0[p], twoa[p], mul2(ue1[p], negq[p]));
                vo1[p] = fma2(vo0[p], twoa[p], mul2(vo1[p], negq[p]));
            }
        }
        __syncthreads();
        // coalesced epilogue: fold the 8 group partials
        const int lbeg = (kbeg + kk0) * NLANE;
        const int lend = lbeg + KCH * NLANE;
        for (int l = lbeg + tid; l < lend && l < L; l += 256) {
            int kk = (l >> 5) - kbeg - kk0, tt = l & 31;
            out[ob + l] = ((sR[kk][0][tt] + sR[kk][1][tt])
                         + (sR[kk][2][tt] + sR[kk][3][tt]))
                        + ((sR[kk][4][tt] + sR[kk][5][tt])
                         + (sR[kk][6][tt] + sR[kk][7][tt]));
        }
        __syncthreads();
    }
}

// ---------------------------------------------------------------------------
extern "C" void kernel_launch(void* const* d_in, const int* in_sizes, int n_in,
                              void* d_out, int out_size) {
    const float* C_real      = (const float*)d_in[0];
    const float* log_dt      = (const float*)d_in[1];
    const float* log_A_real  = (const float*)d_in[2];
    const float* A_imag      = (const float*)d_in[3];
    const float* omega_logit = (const float*)d_in[4];
    const float* eta_logit   = (const float*)d_in[5];

    int H   = in_sizes[1];               // 512
    int NST = in_sizes[2] / H;           // 32
    int L   = out_size / H;              // 2048 (CH = 1)

    dim3 grid(H, NSPLIT);
    loong_fused<<<grid, 256>>>((float*)d_out, C_real, log_dt, log_A_real,
                               A_imag, omega_logit, eta_logit, NST, L);
}

// round 16
// speedup vs baseline: 8.0426x; 8.0426x over previous
#include <cuda_runtime.h>
#include <cuda_bf16.h>

// ---------------------------------------------------------------------------
// LoongSpikeKernel via warp-level bf16 MMA (HMMA; tcgen05 unavailable: harness
// PTX targets plain sm_103, no 'a' features).
//
// K[h, l] = 2*Re( sum_n C_disc[h,n] * exp(dtA[h,n] * l) ),  l = 16*m + d:
//   D[m,d] = sum_n Wr[m,n]*Er[d,n] + (-Wi[m,n])*Ei[d,n]
//   W[m,n] = 2*C_disc[n] * r16[n]^m   (r16 = exp(16*dtA)),  E[d,n] = r1[n]^d
// Split each factor hi+lo bf16 -> 6 term-GEMMs m128 n16 k64 per h, f32 accum.
// One CTA (256 thr) per h: 4 roles x 64 states build W (32-step chains,
// seeded at m=32r), E built per-element; 8 warps run mma.sync m16n8k16.
// Tiles use 144B padded rows: conflict-free ldmatrix without swizzle.
// ---------------------------------------------------------------------------

typedef unsigned int uint;

#define RSTRIDE 144
static constexpr int ATILE = 128 * RSTRIDE;          // 18432 B
static constexpr int BTILE = 16 * RSTRIDE;           // 2304 B
static constexpr int B_OFF = 4 * ATILE;              // 73728
static constexpr int SMEM_TOTAL = B_OFF + 4 * BTILE; // 82944

// fp32 two-term Cody-Waite reduction + fast sincos.
static __device__ __forceinline__ void sincos_cw(float x, float* s, float* c) {
    float k = rintf(x * 0.15915494309189535f);
    float r = fmaf(k, -6.28125f, x);
    r = fmaf(k, -1.9353071795864769e-3f, r);
    __sincosf(r, s, c);
}

static __device__ __forceinline__ uint smem_u32(const void* p) {
    uint r;
    asm("{ .reg .u64 t; cvta.to.shared.u64 t, %1; cvt.u32.u64 %0, t; }"
        : "=r"(r) : "l"(p));
    return r;
}

// split-store: hi = bf16(x), lo = bf16(x - hi)
static __device__ __forceinline__ void st_pair(char* bhi, char* blo, int off, float x) {
    __nv_bfloat16 hb = __float2bfloat16_rn(x);
    *reinterpret_cast<__nv_bfloat16*>(bhi + off) = hb;
    *reinterpret_cast<__nv_bfloat16*>(blo + off) =
        __float2bfloat16_rn(x - __bfloat162float(hb));
}

static __device__ __forceinline__ void ldmA(uint addr, uint& a0, uint& a1,
                                            uint& a2, uint& a3) {
    asm volatile("ldmatrix.sync.aligned.m8n8.x4.shared.b16 {%0,%1,%2,%3}, [%4];"
                 : "=r"(a0), "=r"(a1), "=r"(a2), "=r"(a3) : "r"(addr));
}
static __device__ __forceinline__ void ldmB(uint addr, uint& b0, uint& b1) {
    asm volatile("ldmatrix.sync.aligned.m8n8.x2.shared.b16 {%0,%1}, [%2];"
                 : "=r"(b0), "=r"(b1) : "r"(addr));
}
static __device__ __forceinline__ void mma16816(float* c, uint a0, uint a1,
                                                uint a2, uint a3, uint b0, uint b1) {
    asm volatile(
        "mma.sync.aligned.m16n8k16.row.col.f32.bf16.bf16.f32 "
        "{%0,%1,%2,%3}, {%4,%5,%6,%7}, {%8,%9}, {%0,%1,%2,%3};"
        : "+f"(c[0]), "+f"(c[1]), "+f"(c[2]), "+f"(c[3])
        : "r"(a0), "r"(a1), "r"(a2), "r"(a3), "r"(b0), "r"(b1));
}

extern __shared__ char smem_dyn[];

__global__ __launch_bounds__(256) void loong_hmma(
    float* __restrict__ out,
    const float* __restrict__ C_real,
    const float* __restrict__ log_dt,
    const float* __restrict__ log_A_real,
    const float* __restrict__ A_imag,
    const float* __restrict__ omega_logit,
    const float* __restrict__ eta_logit,
    int NST, int L) {
    const float OMIN = 1e-6f, OMAX = 100.0f, EMIN = 1e-6f, EMAX = 10.0f;
    const int h    = blockIdx.x;
    const int tid  = threadIdx.x;
    const int n    = tid & 63;          // state
    const int role = tid >> 6;          // 0..3: W rows [32*role, 32*role+32)

    __shared__ float2 s_dtA[64];

    // ---- per-state constants (redundant across roles) ----
    const int mi = n / NST;
    const int gi = h * NST + (n - mi * NST);

    float dt    = expf(log_dt[h]);
    float omega = OMIN + (OMAX - OMIN) / (1.f + expf(-omega_logit[mi]));
    float eta   = EMIN + (EMAX - EMIN) / (1.f + expf(-eta_logit[mi]));
    float Are   = -expf(log_A_real[gi]);
    float Aim   = A_imag[gi];
    float Afr   = -omega + eta * Are;
    float Afi   = eta * Aim;
    float Cr    = eta * C_real[gi * 2 + 0];     // CH = 1
    float Ci    = eta * C_real[gi * 2 + 1];
    float dtAr  = Afr * dt;
    float dtAi  = Afi * dt;

    // C_disc = C * (exp(dtA) - 1) / (A_frac + 1e-8)   (small-|A| fallback)
    float er = expf(dtAr);
    float s1, c1; sincos_cw(dtAi, &s1, &c1);
    float nr = er * c1 - 1.f;
    float ni = er * s1;
    float ddr = Afr + 1e-8f, ddi = Afi;
    float inv = 1.f / (ddr * ddr + ddi * ddi);
    float qr  = (nr * ddr + ni * ddi) * inv;
    float qi  = (ni * ddr - nr * ddi) * inv;
    float Cdr = Cr * qr - Ci * qi;
    float Cdi = Cr * qi + Ci * qr;
    if (sqrtf(Afr * Afr + Afi * Afi) < 1e-6f) { Cdr = Cr * dt; Cdi = Ci * dt; }
    float C2r = 2.f * Cdr, C2i = 2.f * Cdi;

    if (tid < 64) s_dtA[tid] = make_float2(dtAr, dtAi);

    // r16 = exp(16*dtA)
    float e16 = __expf(16.f * dtAr);
    float s16, c16; sincos_cw(16.f * dtAi, &s16, &c16);
    float r16r = e16 * c16, r16i = e16 * s16;

    char* Wrh = smem_dyn;
    char* Wrl = smem_dyn + ATILE;
    char* Wih = smem_dyn + 2 * ATILE;   // holds -Wi
    char* Wil = smem_dyn + 3 * ATILE;
    char* Erh = smem_dyn + B_OFF;
    char* Erl = smem_dyn + B_OFF + BTILE;
    char* Eih = smem_dyn + B_OFF + 2 * BTILE;
    char* Eil = smem_dyn + B_OFF + 3 * BTILE;

    // ---- W chain: rows m = 32*role .. 32*role+31, column n ----
    float wr, wi;
    if (role == 0) { wr = C2r; wi = C2i; }
    else {
        float a = 512.f * (float)role;          // 16 * 32 * role
        float eS = __expf(a * dtAr);
        float sS, cS; sincos_cw(a * dtAi, &sS, &cS);
        float pr = eS * cS, pi = eS * sS;
        wr = C2r * pr - C2i * pi;
        wi = C2r * pi + C2i * pr;
    }
#pragma unroll 4
    for (int m = 32 * role; m < 32 * role + 32; m++) {
        int off = m * RSTRIDE + n * 2;
        st_pair(Wrh, Wrl, off, wr);
        st_pair(Wih, Wil, off, -wi);
        float tr = wr * r16r - wi * r16i;
        wi = wr * r16i + wi * r16r;
        wr = tr;
    }
    __syncthreads();                             // s_dtA visible

    // ---- E tile: entry (d, n2) = exp(d * dtA);  4 entries per thread ----
    {
        const int d  = tid >> 4;                 // 0..15
        const int n0 = (tid & 15) * 4;
        const float df = (float)d;
#pragma unroll
        for (int j = 0; j < 4; j++) {
            int n2 = n0 + j;
            float2 a = s_dtA[n2];
            float ee = __expf(df * a.x);
            float ss, cc; sincos_cw(df * a.y, &ss, &cc);
            int off = d * RSTRIDE + n2 * 2;
            st_pair(Erh, Erl, off, ee * cc);
            st_pair(Eih, Eil, off, ee * ss);
        }
    }
    __syncthreads();                             // all tiles ready

    // ---- GEMM: 8 warps x (16 rows x 16 cols), K=64, 6 terms ----
    const int lane = tid & 31;
    const int m0   = (tid >> 5) * 16;
    const uint base = smem_u32(smem_dyn);
    const uint AoffL = (uint)((m0 + (lane & 15)) * RSTRIDE + ((lane >> 4) << 4));
    const uint BoffL = (uint)((lane & 7) * RSTRIDE + (((lane >> 3) & 1) << 4));

    float c0[4] = {0.f, 0.f, 0.f, 0.f};
    float cn[4] = {0.f, 0.f, 0.f, 0.f};
    const int ta[6] = {0, 0, 1, 2, 2, 3};        // Wrh,Wrh,Wrl,Wih,Wih,Wil
    const int tb[6] = {0, 1, 0, 2, 3, 2};        // Erh,Erl,Erh,Eih,Eil,Eih
#pragma unroll
    for (int t6 = 0; t6 < 6; t6++) {
        uint Ab = base + ta[t6] * ATILE + AoffL;
        uint Bb = base + B_OFF + tb[t6] * BTILE + BoffL;
#pragma unroll
        for (int k0 = 0; k0 < 64; k0 += 16) {
            uint a0, a1, a2, a3, b0, b1, b2, b3;
            ldmA(Ab + k0 * 2, a0, a1, a2, a3);
            ldmB(Bb + k0 * 2, b0, b1);                       // ntile 0 (d 0..7)
            ldmB(Bb + 8 * RSTRIDE + k0 * 2, b2, b3);         // ntile 1 (d 8..15)
            mma16816(c0, a0, a1, a2, a3, b0, b1);
            mma16816(cn, a0, a1, a2, a3, b2, b3);
        }
    }

    // ---- store: D[r][c] -> out[h*L + 16*r + c] ----
    const int r0 = m0 + (lane >> 2);
    const int cc = (lane & 3) * 2;
    float* op = out + (size_t)h * L;
    *reinterpret_cast<float2*>(op + 16 * r0 + cc)           = make_float2(c0[0], c0[1]);
    *reinterpret_cast<float2*>(op + 16 * (r0 + 8) + cc)     = make_float2(c0[2], c0[3]);
    *reinterpret_cast<float2*>(op + 16 * r0 + 8 + cc)       = make_float2(cn[0], cn[1]);
    *reinterpret_cast<float2*>(op + 16 * (r0 + 8) + 8 + cc) = make_float2(cn[2], cn[3]);
}

// ---------------------------------------------------------------------------
extern "C" void kernel_launch(void* const* d_in, const int* in_sizes, int n_in,
                              void* d_out, int out_size) {
    const float* C_real      = (const float*)d_in[0];
    const float* log_dt      = (const float*)d_in[1];
    const float* log_A_real  = (const float*)d_in[2];
    const float* A_imag      = (const float*)d_in[3];
    const float* omega_logit = (const float*)d_in[4];
    const float* eta_logit   = (const float*)d_in[5];

    int H   = in_sizes[1];               // 512
    int NST = in_sizes[2] / H;           // 32
    int L   = out_size / H;              // 2048 = 128*16 (CH = 1)

    static bool attr_set = false;
    if (!attr_set) {
        cudaFuncSetAttribute(loong_hmma,
                             cudaFuncAttributeMaxDynamicSharedMemorySize,
                             SMEM_TOTAL);
        attr_set = true;
    }
    loong_hmma<<<H, 256, SMEM_TOTAL>>>((float*)d_out, C_real, log_dt,
                                       log_A_real, A_imag, omega_logit,
                                       eta_logit, NST, L);
}